// round 15
// baseline (speedup 1.0000x reference)
#include <cuda_runtime.h>
#include <math.h>
#include <stdint.h>

#define Bsz 1024
#define Nn  100
#define Hh  256
#define H3  768
#define NBLK 128
#define NT  512
#define CLSZ 8
#define HR  260   // padded row stride (floats)

// ---------------- static device scratch ----------------
__device__ float g_G[Bsz*Nn*H3];      // enc @ W1T + b_ih1
__device__ float g_ref[Bsz*Nn*Hh];    // enc @ W_ref
__device__ float g_G0[Bsz*H3];
__device__ float g_mean[Bsz*Hh];
__device__ float g_W1T[Hh*H3];        // [k][j] for precompute GEMM
__device__ float g_WqT[Hh*Hh];        // [j][k]
__device__ float g_bias0[H3];
__device__ float g_wD[H3];
__device__ __align__(256) float g_h1x[16*64*HR];   // padded h1 exchange
__device__ __align__(256) float g_h2x[16*64*HR];   // padded h2 exchange
__device__ __align__(256) float g_qx[Bsz*Hh];      // q exchange

// ---------------- math helpers ----------------
__device__ __forceinline__ float fast_tanh(float x) {
    float ax = fabsf(x);
    float e  = __expf(-2.0f * ax);
    float t  = __fdividef(1.0f - e, 1.0f + e);
    return copysignf(t, x);
}
__device__ __forceinline__ float sigmoidf_(float x) {
    return __fdividef(1.0f, 1.0f + __expf(-x));
}
__device__ __forceinline__ float tanh4dot(float4 q, float4 r, float4 v) {
    const float C = -2.8853900817779268f;   // -2*log2(e)
    float x0=q.x+r.x, x1=q.y+r.y, x2=q.z+r.z, x3=q.w+r.w;
    float e0=exp2f(fabsf(x0)*C), e1=exp2f(fabsf(x1)*C);
    float e2=exp2f(fabsf(x2)*C), e3=exp2f(fabsf(x3)*C);
    float a0=1.f+e0, a1=1.f+e1, a2=1.f+e2, a3=1.f+e3;
    float m0=(1.f-e0)*v.x, m1=(1.f-e1)*v.y, m2=(1.f-e2)*v.z, m3=(1.f-e3)*v.w;
    m0=__uint_as_float(__float_as_uint(m0)^(__float_as_uint(x0)&0x80000000u));
    m1=__uint_as_float(__float_as_uint(m1)^(__float_as_uint(x1)&0x80000000u));
    m2=__uint_as_float(__float_as_uint(m2)^(__float_as_uint(x2)&0x80000000u));
    m3=__uint_as_float(__float_as_uint(m3)^(__float_as_uint(x3)&0x80000000u));
    float p01=a0*a1, p23=a2*a3, d=p01*p23, rd;
    asm("rcp.approx.f32 %0, %1;" : "=f"(rd) : "f"(d));
    float num = fmaf(fmaf(m0,a1,m1*a0), p23, fmaf(m2,a3,m3*a2)*p01);
    return num * rd;
}
__device__ __forceinline__ float dot4(float4 a, float4 b, float acc) {
    acc = fmaf(a.x, b.x, acc); acc = fmaf(a.y, b.y, acc);
    acc = fmaf(a.z, b.z, acc); acc = fmaf(a.w, b.w, acc);
    return acc;
}

// ---------------- TMA-bulk / mbarrier / cluster helpers ----------------
__device__ __forceinline__ uint32_t smem_u32(const void* p) {
    uint32_t a;
    asm("{ .reg .u64 t; cvta.to.shared.u64 t, %1; cvt.u32.u64 %0, t; }" : "=r"(a) : "l"(p));
    return a;
}
__device__ __forceinline__ void mbar_init(uint32_t a, uint32_t cnt) {
    asm volatile("mbarrier.init.shared.b64 [%0], %1;" :: "r"(a), "r"(cnt) : "memory");
}
__device__ __forceinline__ void mbar_expect_tx(uint32_t a, uint32_t bytes) {
    asm volatile("mbarrier.arrive.expect_tx.shared.b64 _, [%0], %1;" :: "r"(a), "r"(bytes) : "memory");
}
__device__ __forceinline__ void bulk_g2s(uint32_t dst, const float* src, uint32_t bytes, uint32_t mbar) {
    asm volatile("cp.async.bulk.shared::cluster.global.mbarrier::complete_tx::bytes [%0], [%1], %2, [%3];"
                 :: "r"(dst), "l"(src), "r"(bytes), "r"(mbar) : "memory");
}
__device__ __forceinline__ void mbar_wait(uint32_t a, uint32_t par) {
    asm volatile("{ .reg .pred P; WL%=:"
                 " mbarrier.try_wait.parity.acquire.cta.shared::cta.b64 P, [%0], %1, 0x989680;"
                 " @P bra WD%=; bra WL%=; WD%=: }"
                 :: "r"(a), "r"(par) : "memory");
}
#define CLUSTER_SYNC_() do { \
    asm volatile("barrier.cluster.arrive.aligned;" ::: "memory"); \
    asm volatile("barrier.cluster.wait.aligned;" ::: "memory"); } while (0)

// ---------------- precompute kernels ----------------
__global__ void k_prep(const float* __restrict__ W_ih1,
                       const float* __restrict__ W_q,
                       const float* __restrict__ b_ih1) {
    int i = blockIdx.x * 256 + threadIdx.x;    // 768 blocks -> 196608
    if (i < Hh*H3) {
        int k = i / H3, j = i % H3;
        g_W1T[i] = W_ih1[j*257 + k];
    }
    if (i < Hh*Hh) {
        int j = i >> 8, k = i & 255;
        g_WqT[i] = W_q[k*256 + j];
    }
    if (i < H3) {
        float wd = W_ih1[i*257 + 256];
        g_wD[i] = wd;
        g_bias0[i] = b_ih1[i] + wd;
    }
}

__global__ void k_mean(const float* __restrict__ enc) {
    int b = blockIdx.x, h = threadIdx.x;
    float s = 0.f;
    for (int n = 0; n < Nn; n++) s += enc[(b*Nn + n)*Hh + h];
    g_mean[b*Hh + h] = s / (float)Nn;
}

template<int BM, int BN, int TM, int TN>
__global__ __launch_bounds__(256)
void k_sgemm(const float* __restrict__ A, const float* __restrict__ Bm,
             const float* __restrict__ bias, float* __restrict__ C,
             int M, int N, int K) {
    const int BK = 16;
    __shared__ float As[BK][BM];
    __shared__ float Bs[BK][BN];
    int tid = threadIdx.x;
    int tx = tid % (BN/TN), ty = tid / (BN/TN);
    int m0 = blockIdx.y * BM, n0 = blockIdx.x * BN;
    float acc[TM][TN];
#pragma unroll
    for (int i = 0; i < TM; i++)
#pragma unroll
        for (int j = 0; j < TN; j++) acc[i][j] = 0.f;
    for (int k0 = 0; k0 < K; k0 += BK) {
#pragma unroll
        for (int r = 0; r < (BM*BK)/1024; r++) {
            int idx = tid + r*256, mm = idx/(BK/4), kk4 = idx%(BK/4);
            float4 a = *(const float4*)&A[(size_t)(m0+mm)*K + k0 + kk4*4];
            As[kk4*4+0][mm]=a.x; As[kk4*4+1][mm]=a.y; As[kk4*4+2][mm]=a.z; As[kk4*4+3][mm]=a.w;
        }
#pragma unroll
        for (int r = 0; r < (BK*BN)/1024; r++) {
            int idx = tid + r*256, kk = idx/(BN/4), nn4 = idx%(BN/4);
            *(float4*)&Bs[kk][nn4*4] = *(const float4*)&Bm[(size_t)(k0+kk)*N + n0 + nn4*4];
        }
        __syncthreads();
#pragma unroll
        for (int kk = 0; kk < BK; kk++) {
            float ra[TM], rb[TN];
#pragma unroll
            for (int i = 0; i < TM; i += 4) *(float4*)&ra[i] = *(float4*)&As[kk][ty*TM+i];
#pragma unroll
            for (int j = 0; j < TN; j += 4) *(float4*)&rb[j] = *(float4*)&Bs[kk][tx*TN+j];
#pragma unroll
            for (int i = 0; i < TM; i++)
#pragma unroll
                for (int j = 0; j < TN; j++) acc[i][j] += ra[i]*rb[j];
        }
        __syncthreads();
    }
#pragma unroll
    for (int i = 0; i < TM; i++) {
        int m = m0 + ty*TM + i;
#pragma unroll
        for (int j = 0; j < TN; j += 4) {
            int n = n0 + tx*TN + j;
            float4 r;
            r.x = acc[i][j+0] + (bias ? bias[n+0] : 0.f);
            r.y = acc[i][j+1] + (bias ? bias[n+1] : 0.f);
            r.z = acc[i][j+2] + (bias ? bias[n+2] : 0.f);
            r.w = acc[i][j+3] + (bias ? bias[n+3] : 0.f);
            *(float4*)&C[(size_t)m*N + n] = r;
        }
    }
}

// ---------------- cluster decode loop: resident weights, global+TMA exchange ----------------
// smem floats: w2s 3*32*260 | wqs 32*260 | hx 64*260 | q 2048 | v 256 | su 800
#define OF_W2S 0
#define OF_WQS (OF_W2S + 3*32*HR)      // 24960
#define OF_HX  (OF_WQS + 32*HR)        // 33280
#define OF_Q   (OF_HX + 64*HR)         // 49920
#define OF_V   (OF_Q + 2048)           // 51968
#define OF_SU  (OF_V + 256)            // 52224
#define OF_END (OF_SU + 800)           // 53024
#define MBAR_OFF_BYTES (OF_END*4 + 32 + 800 + 800)   // nxt + cand + pi
#define SMEM_BYTES (MBAR_OFF_BYTES + 8)

__global__ __launch_bounds__(NT, 1) __cluster_dims__(CLSZ, 1, 1)
void k_loop(const float* __restrict__ G,  const float* __restrict__ G0,
            const float* __restrict__ REF,
            const float* __restrict__ W_ih2, const float* __restrict__ WqT,
            const float* __restrict__ b_hh1,
            const float* __restrict__ b_ih2, const float* __restrict__ b_hh2,
            const float* __restrict__ v,   const float* __restrict__ wD,
            const float* __restrict__ x,
            float* __restrict__ H1X, float* __restrict__ H2X, float* __restrict__ QX,
            float* __restrict__ out) {
    extern __shared__ float sm[];
    float* w2s  = sm + OF_W2S;
    float* wqs  = sm + OF_WQS;
    float* hx   = sm + OF_HX;
    float* sh_q = sm + OF_Q;
    float* sh_v = sm + OF_V;
    float* sh_su = sm + OF_SU;
    int*   sh_nxt = (int*)(sm + OF_END);
    unsigned char* sh_cand = (unsigned char*)(sh_nxt + 8);
    unsigned char* sh_pi   = sh_cand + 800;

    const uint32_t base = smem_u32(sm);
    const uint32_t HXa = base + OF_HX*4;
    const uint32_t QAa = base + OF_Q*4;
    const uint32_t MB  = base + MBAR_OFF_BYTES;

    const int tid = threadIdx.x, lane = tid & 31, w = tid >> 5;
    const int bid = blockIdx.x;
    const int cl = bid >> 3, rk = bid & 7;       // cluster id, rank
    const int b0 = bid * 8;                      // my 8 global batch rows
    const int cbase = cl * 64;                   // cluster-global row base

    // ---- one-time init ----
    for (int i = tid; i < 800; i += NT) sh_cand[i] = (unsigned char)(i % 100);
    if (tid < 256) sh_v[tid] = __ldg(v + tid);
    // resident weight slices (cols [32*rk, 32*rk+32))
    for (int i = tid; i < 3*32*256; i += NT) {
        int k = i & 255, col = (i >> 8) & 31, g = i >> 13;
        w2s[(g*32 + col)*HR + k] = __ldg(&W_ih2[(g*256 + rk*32 + col)*256 + k]);
    }
    for (int i = tid; i < 32*256; i += NT) {
        int k = i & 255, col = i >> 8;
        wqs[col*HR + k] = __ldg(&WqT[(rk*32 + col)*256 + k]);
    }
    // GRU2 biases for my two columns per warp
    const int c0 = rk*32 + 2*w, c1 = c0 + 1;
    const float biR0=__ldg(b_ih2+c0),     biR1=__ldg(b_ih2+c1);
    const float biZ0=__ldg(b_ih2+256+c0), biZ1=__ldg(b_ih2+256+c1);
    const float biN0=__ldg(b_ih2+512+c0), biN1=__ldg(b_ih2+512+c1);
    const float bhR0=__ldg(b_hh2+c0),     bhR1=__ldg(b_hh2+c1);
    const float bhZ0=__ldg(b_hh2+256+c0), bhZ1=__ldg(b_hh2+256+c1);
    const float bhN0=__ldg(b_hh2+512+c0), bhN1=__ldg(b_hh2+512+c1);

    if (tid == 0) mbar_init(MB, 1);
    __syncthreads();
    CLUSTER_SYNC_();

    float Dv = 1.0f, ll = 0.0f;
    unsigned mpc = 0;   // mbar use counter (parity)

#pragma unroll 1
    for (int t = 0; t < Nn; t++) {
        // ---- A: GRU1 (h=0) for my 8 rows -> STG to padded H1X ----
#pragma unroll
        for (int c = 0; c < 4; c++) {
            int idx = tid + c*NT;              // 2048 outputs
            int row = idx >> 8, j = idx & 255;
            const float* gsrc = (t == 0) ? (G0 + (size_t)(b0 + row)*H3)
                                         : (G + ((size_t)(b0 + row)*Nn + sh_nxt[row])*H3);
            float gr = __ldg(gsrc+j), gz = __ldg(gsrc+j+256), gn = __ldg(gsrc+j+512);
            if (t > 0) {
                gr = fmaf(Dv, __ldg(wD+j),     gr);
                gz = fmaf(Dv, __ldg(wD+j+256), gz);
                gn = fmaf(Dv, __ldg(wD+j+512), gn);
            }
            float rr = sigmoidf_(gr + __ldg(b_hh1+j));
            float zz = sigmoidf_(gz + __ldg(b_hh1+j+256));
            float nn = fast_tanh(fmaf(rr, __ldg(b_hh1+j+512), gn));
            H1X[(size_t)(cbase + rk*8 + row)*HR + j] = (1.f - zz) * nn;
        }
        __threadfence();
        CLUSTER_SYNC_();
        if (tid == 0) {
            mbar_expect_tx(MB, 64*HR*4);
            bulk_g2s(HXa, H1X + (size_t)cbase*HR, 64*HR*4, MB);
        }
        mbar_wait(MB, mpc & 1); mpc++;

        // ---- B: gi2 slice (cols [32rk,32rk+32) x3 gates) for 64 rows + GRU2 -> H2X ----
        {
            float aR0[2], aR1[2], aZ0[2], aZ1[2], aN0[2], aN1[2];
#pragma unroll
            for (int m = 0; m < 2; m++) { aR0[m]=aR1[m]=aZ0[m]=aZ1[m]=aN0[m]=aN1[m]=0.f; }
            const float* wR0 = w2s + (0*32 + 2*w)*HR;
            const float* wR1 = wR0 + HR;
            const float* wZ0 = w2s + (1*32 + 2*w)*HR;
            const float* wZ1 = wZ0 + HR;
            const float* wN0 = w2s + (2*32 + 2*w)*HR;
            const float* wN1 = wN0 + HR;
            const float* a0p = hx + lane*HR;
            const float* a1p = hx + (lane + 32)*HR;
#pragma unroll 4
            for (int k4 = 0; k4 < 64; k4++) {
                float4 br0 = *(const float4*)(wR0 + k4*4);
                float4 br1 = *(const float4*)(wR1 + k4*4);
                float4 bz0 = *(const float4*)(wZ0 + k4*4);
                float4 bz1 = *(const float4*)(wZ1 + k4*4);
                float4 bn0 = *(const float4*)(wN0 + k4*4);
                float4 bn1 = *(const float4*)(wN1 + k4*4);
                float4 a0 = *(const float4*)(a0p + k4*4);
                float4 a1 = *(const float4*)(a1p + k4*4);
                aR0[0]=dot4(a0,br0,aR0[0]); aR0[1]=dot4(a1,br0,aR0[1]);
                aR1[0]=dot4(a0,br1,aR1[0]); aR1[1]=dot4(a1,br1,aR1[1]);
                aZ0[0]=dot4(a0,bz0,aZ0[0]); aZ0[1]=dot4(a1,bz0,aZ0[1]);
                aZ1[0]=dot4(a0,bz1,aZ1[0]); aZ1[1]=dot4(a1,bz1,aZ1[1]);
                aN0[0]=dot4(a0,bn0,aN0[0]); aN0[1]=dot4(a1,bn0,aN0[1]);
                aN1[0]=dot4(a0,bn1,aN1[0]); aN1[1]=dot4(a1,bn1,aN1[1]);
            }
#pragma unroll
            for (int m = 0; m < 2; m++) {
                int row = lane + 32*m;
                float r0 = sigmoidf_((aR0[m] + biR0) + bhR0);
                float z0 = sigmoidf_((aZ0[m] + biZ0) + bhZ0);
                float n0 = fast_tanh(fmaf(r0, bhN0, aN0[m] + biN0));
                H2X[(size_t)(cbase + row)*HR + c0] = (1.f - z0) * n0;
                float r1 = sigmoidf_((aR1[m] + biR1) + bhR1);
                float z1 = sigmoidf_((aZ1[m] + biZ1) + bhZ1);
                float n1 = fast_tanh(fmaf(r1, bhN1, aN1[m] + biN1));
                H2X[(size_t)(cbase + row)*HR + c1] = (1.f - z1) * n1;
            }
        }
        __threadfence();
        CLUSTER_SYNC_();
        if (tid == 0) {
            mbar_expect_tx(MB, 64*HR*4);
            bulk_g2s(HXa, H2X + (size_t)cbase*HR, 64*HR*4, MB);
        }
        mbar_wait(MB, mpc & 1); mpc++;

        // ---- C: q slice (cols [32rk,32rk+32)) for 64 rows -> QX ----
        {
            float q0a[2], q1a[2];
#pragma unroll
            for (int m = 0; m < 2; m++) { q0a[m]=0.f; q1a[m]=0.f; }
            const float* wq0 = wqs + (2*w)*HR;
            const float* wq1 = wq0 + HR;
            const float* a0p = hx + lane*HR;
            const float* a1p = hx + (lane + 32)*HR;
#pragma unroll 4
            for (int k4 = 0; k4 < 64; k4++) {
                float4 b0 = *(const float4*)(wq0 + k4*4);
                float4 b1 = *(const float4*)(wq1 + k4*4);
                float4 a0 = *(const float4*)(a0p + k4*4);
                float4 a1 = *(const float4*)(a1p + k4*4);
                q0a[0]=dot4(a0,b0,q0a[0]); q0a[1]=dot4(a1,b0,q0a[1]);
                q1a[0]=dot4(a0,b1,q1a[0]); q1a[1]=dot4(a1,b1,q1a[1]);
            }
#pragma unroll
            for (int m = 0; m < 2; m++) {
                int row = lane + 32*m;
                QX[(size_t)(cbase + row)*Hh + c0] = q0a[m];
                QX[(size_t)(cbase + row)*Hh + c1] = q1a[m];
            }
        }
        __threadfence();
        CLUSTER_SYNC_();
        if (tid == 0) {
            mbar_expect_tx(MB, 8*Hh*4);
            bulk_g2s(QAa, QX + (size_t)b0*Hh, 8*Hh*4, MB);
        }
        mbar_wait(MB, mpc & 1); mpc++;

        // ---- D: attention over candidate list, 2 warps/row, pipelined loads ----
        {
            const int w2i = w >> 1, parr = w & 1;
            const int cnt = Nn - t;
            const int R = b0 + w2i;
            float4 q0 = *(const float4*)(sh_q + w2i*256 + lane*4);
            float4 q1 = *(const float4*)(sh_q + w2i*256 + 128 + lane*4);
            float4 v0 = *(const float4*)(sh_v + lane*4);
            float4 v1 = *(const float4*)(sh_v + 128 + lane*4);
            const float4* refrow = (const float4*)(REF + (size_t)R*Nn*Hh);
            const unsigned char* cdl = sh_cand + w2i*100;
            int i = parr;
            float4 ra, rb;
            if (i < cnt) {
                int n0i = cdl[i];
                ra = __ldg(refrow + n0i*64 + lane);
                rb = __ldg(refrow + n0i*64 + 32 + lane);
            }
#pragma unroll 1
            for (; i < cnt; i += 2) {
                int nnx = (i + 2 < cnt) ? cdl[i + 2] : 0;
                float4 ra2 = __ldg(refrow + nnx*64 + lane);
                float4 rb2 = __ldg(refrow + nnx*64 + 32 + lane);
                float s = tanh4dot(q0, ra, v0) + tanh4dot(q1, rb, v1);
#pragma unroll
                for (int o = 16; o; o >>= 1) s += __shfl_xor_sync(~0u, s, o);
                if (lane == 0) sh_su[w2i*100 + i] = 10.f * fast_tanh(s);
                ra = ra2; rb = rb2;
            }
        }
        __syncthreads();
        // argmax / log-softmax / state: warp w handles row w (w < 8)
        if (w < 8) {
            const int cnt = Nn - t;
            float best = -INFINITY; int bidx = 0x7fffffff; int bpos = 0;
            for (int i = lane; i < cnt; i += 32) {
                float u = sh_su[w*100 + i];
                int n = sh_cand[w*100 + i];
                if (u > best || (u == best && n < bidx)) { best = u; bidx = n; bpos = i; }
            }
#pragma unroll
            for (int o = 16; o; o >>= 1) {
                float ov = __shfl_xor_sync(~0u, best, o);
                int   oi = __shfl_xor_sync(~0u, bidx, o);
                int   op = __shfl_xor_sync(~0u, bpos, o);
                if (ov > best || (ov == best && oi < bidx)) { best = ov; bidx = oi; bpos = op; }
            }
            float se = 0.f;
            for (int i = lane; i < cnt; i += 32) se += __expf(sh_su[w*100 + i] - best);
#pragma unroll
            for (int o = 16; o; o >>= 1) se += __shfl_xor_sync(~0u, se, o);
            ll += -__logf(se);
            if (lane == 0) {
                sh_nxt[w] = bidx;
                sh_pi[w*100 + t] = (unsigned char)bidx;
                sh_cand[w*100 + bpos] = sh_cand[w*100 + cnt - 1];   // swap-remove
            }
        }
        __syncthreads();
        Dv -= 0.01f;
    }

    // ---- tour cost + output: warp w handles row w (w < 8) ----
    if (w < 8) {
        float cs = 0.f;
        const float* xb = x + (size_t)(b0 + w)*Nn*2;
        for (int tt = lane; tt < Nn; tt += 32) {
            int a  = sh_pi[w*100 + tt];
            int cc = sh_pi[w*100 + ((tt == Nn-1) ? 0 : tt+1)];
            float dx = __ldg(xb + a*2)     - __ldg(xb + cc*2);
            float dy = __ldg(xb + a*2 + 1) - __ldg(xb + cc*2 + 1);
            cs += sqrtf(dx*dx + dy*dy);
        }
#pragma unroll
        for (int o = 16; o; o >>= 1) cs += __shfl_xor_sync(~0u, cs, o);
        if (lane == 0) { out[b0 + w] = cs; out[Bsz + b0 + w] = ll; }
    }
    CLUSTER_SYNC_();   // uniform exit
}

// ---------------- launcher ----------------
extern "C" void kernel_launch(void* const* d_in, const int* in_sizes, int n_in,
                              void* d_out, int out_size) {
    const float* x     = (const float*)d_in[0];
    const float* enc   = (const float*)d_in[1];
    const float* W_ih1 = (const float*)d_in[2];
    const float* b_ih1 = (const float*)d_in[4];
    const float* b_hh1 = (const float*)d_in[5];
    const float* W_ih2 = (const float*)d_in[6];
    const float* b_ih2 = (const float*)d_in[8];
    const float* b_hh2 = (const float*)d_in[9];
    const float* W_q   = (const float*)d_in[10];
    const float* W_ref = (const float*)d_in[11];
    const float* v     = (const float*)d_in[12];
    float* out = (float*)d_out;

    float *G, *REF, *G0, *MEAN, *W1T, *WqT, *BIAS0, *WD, *H1X, *H2X, *QX;
    cudaGetSymbolAddress((void**)&G,    g_G);
    cudaGetSymbolAddress((void**)&REF,  g_ref);
    cudaGetSymbolAddress((void**)&G0,   g_G0);
    cudaGetSymbolAddress((void**)&MEAN, g_mean);
    cudaGetSymbolAddress((void**)&W1T,  g_W1T);
    cudaGetSymbolAddress((void**)&WqT,  g_WqT);
    cudaGetSymbolAddress((void**)&BIAS0,g_bias0);
    cudaGetSymbolAddress((void**)&WD,   g_wD);
    cudaGetSymbolAddress((void**)&H1X,  g_h1x);
    cudaGetSymbolAddress((void**)&H2X,  g_h2x);
    cudaGetSymbolAddress((void**)&QX,   g_qx);

    cudaFuncSetAttribute(k_loop, cudaFuncAttributeMaxDynamicSharedMemorySize, SMEM_BYTES);
    cudaFuncSetAttribute(k_loop, cudaFuncAttributeNonPortableClusterSizeAllowed, 1);

    k_prep<<<768, 256>>>(W_ih1, W_q, b_ih1);
    k_mean<<<Bsz, 256>>>(enc);
    k_sgemm<128,128,8,8><<<dim3(H3/128, (Bsz*Nn)/128), 256>>>(enc, W1T, b_ih1, G, Bsz*Nn, H3, Hh);
    k_sgemm<128,128,8,8><<<dim3(Hh/128, (Bsz*Nn)/128), 256>>>(enc, W_ref, nullptr, REF, Bsz*Nn, Hh, Hh);
    k_sgemm<64,64,4,4><<<dim3(H3/64, Bsz/64), 256>>>(MEAN, W1T, BIAS0, G0, Bsz, H3, Hh);
    k_loop<<<NBLK, NT, SMEM_BYTES>>>(G, G0, REF, W_ih2, WqT, b_hh1, b_ih2, b_hh2, v, WD, x,
                                     H1X, H2X, QX, out);
}

// round 17
// speedup vs baseline: 2.0179x; 2.0179x over previous
#include <cuda_runtime.h>
#include <math.h>
#include <stdint.h>

#define Bsz 1024
#define Nn  100
#define Hh  256
#define H3  768
#define NBLK 128
#define NT  512
#define HR  260   // padded row stride (floats) for h1/h2/q

// ---------------- static device scratch ----------------
__device__ float g_G[Bsz*Nn*H3];      // enc @ W1T + b_ih1
__device__ float g_ref[Bsz*Nn*Hh];    // enc @ W_ref
__device__ float g_G0[Bsz*H3];
__device__ float g_mean[Bsz*Hh];
__device__ float g_W1T[Hh*H3];        // [k][j] for precompute GEMM
__device__ __align__(256) float g_W2P[H3*Hh];   // packed: [tk][kk4][j][c]
__device__ __align__(256) float g_WqP[Hh*Hh];   // packed: [tk][kk4][j][c]
__device__ float g_bias0[H3];
__device__ float g_wD[H3];

// ---------------- math helpers ----------------
__device__ __forceinline__ float fast_tanh(float x) {
    float ax = fabsf(x);
    float e  = __expf(-2.0f * ax);
    float t  = __fdividef(1.0f - e, 1.0f + e);
    return copysignf(t, x);
}
__device__ __forceinline__ float sigmoidf_(float x) {
    return __fdividef(1.0f, 1.0f + __expf(-x));
}
__device__ __forceinline__ float tanh4dot(float4 q, float4 r, float4 v) {
    const float C = -2.8853900817779268f;   // -2*log2(e)
    float x0=q.x+r.x, x1=q.y+r.y, x2=q.z+r.z, x3=q.w+r.w;
    float e0=exp2f(fabsf(x0)*C), e1=exp2f(fabsf(x1)*C);
    float e2=exp2f(fabsf(x2)*C), e3=exp2f(fabsf(x3)*C);
    float a0=1.f+e0, a1=1.f+e1, a2=1.f+e2, a3=1.f+e3;
    float m0=(1.f-e0)*v.x, m1=(1.f-e1)*v.y, m2=(1.f-e2)*v.z, m3=(1.f-e3)*v.w;
    m0=__uint_as_float(__float_as_uint(m0)^(__float_as_uint(x0)&0x80000000u));
    m1=__uint_as_float(__float_as_uint(m1)^(__float_as_uint(x1)&0x80000000u));
    m2=__uint_as_float(__float_as_uint(m2)^(__float_as_uint(x2)&0x80000000u));
    m3=__uint_as_float(__float_as_uint(m3)^(__float_as_uint(x3)&0x80000000u));
    float p01=a0*a1, p23=a2*a3, d=p01*p23, rd;
    asm("rcp.approx.f32 %0, %1;" : "=f"(rd) : "f"(d));
    float num = fmaf(fmaf(m0,a1,m1*a0), p23, fmaf(m2,a3,m3*a2)*p01);
    return num * rd;
}
__device__ __forceinline__ float dot4(float4 a, float4 b, float acc) {
    acc = fmaf(a.x, b.x, acc); acc = fmaf(a.y, b.y, acc);
    acc = fmaf(a.z, b.z, acc); acc = fmaf(a.w, b.w, acc);
    return acc;
}

// ---------------- TMA-bulk / mbarrier helpers ----------------
__device__ __forceinline__ uint32_t smem_u32(const void* p) {
    uint32_t a;
    asm("{ .reg .u64 t; cvta.to.shared.u64 t, %1; cvt.u32.u64 %0, t; }" : "=r"(a) : "l"(p));
    return a;
}
__device__ __forceinline__ void mbar_init(uint32_t a, uint32_t cnt) {
    asm volatile("mbarrier.init.shared.b64 [%0], %1;" :: "r"(a), "r"(cnt) : "memory");
}
__device__ __forceinline__ void mbar_expect_tx(uint32_t a, uint32_t bytes) {
    asm volatile("mbarrier.arrive.expect_tx.shared.b64 _, [%0], %1;" :: "r"(a), "r"(bytes) : "memory");
}
__device__ __forceinline__ void mbar_arrive(uint32_t a) {
    asm volatile("mbarrier.arrive.shared.b64 _, [%0];" :: "r"(a) : "memory");
}
__device__ __forceinline__ void bulk_g2s(uint32_t dst, const float* src, uint32_t bytes, uint32_t mbar) {
    asm volatile("cp.async.bulk.shared::cluster.global.mbarrier::complete_tx::bytes [%0], [%1], %2, [%3];"
                 :: "r"(dst), "l"(src), "r"(bytes), "r"(mbar) : "memory");
}
__device__ __forceinline__ void mbar_wait(uint32_t a, uint32_t par) {
    asm volatile("{ .reg .pred P; WL%=:"
                 " mbarrier.try_wait.parity.acquire.cta.shared::cta.b64 P, [%0], %1, 0x989680;"
                 " @P bra WD%=; bra WL%=; WD%=: }"
                 :: "r"(a), "r"(par) : "memory");
}

// ---------------- precompute kernels ----------------
__global__ void k_prep(const float* __restrict__ W_ih1,
                       const float* __restrict__ W_ih2,
                       const float* __restrict__ W_q,
                       const float* __restrict__ b_ih1) {
    int i = blockIdx.x * 256 + threadIdx.x;    // 768 blocks -> 196608
    if (i < Hh*H3) {
        int k = i / H3, j = i % H3;
        g_W1T[i] = W_ih1[j*257 + k];
        int c = i & 3, tmp = i >> 2;
        int jj = tmp % 768, kk4 = (tmp / 768) & 7, tk = tmp / 6144;
        int kk = tk*32 + kk4*4 + c;
        g_W2P[i] = W_ih2[jj*256 + kk];
    }
    if (i < Hh*Hh) {
        int c = i & 3, tmp = i >> 2;
        int jj = tmp & 255, kk4 = (tmp >> 8) & 7, tk = tmp >> 11;
        int kk = tk*32 + kk4*4 + c;
        g_WqP[i] = W_q[kk*256 + jj];
    }
    if (i < H3) {
        float wd = W_ih1[i*257 + 256];
        g_wD[i] = wd;
        g_bias0[i] = b_ih1[i] + wd;
    }
}

__global__ void k_mean(const float* __restrict__ enc) {
    int b = blockIdx.x, h = threadIdx.x;
    float s = 0.f;
    for (int n = 0; n < Nn; n++) s += enc[(b*Nn + n)*Hh + h];
    g_mean[b*Hh + h] = s / (float)Nn;
}

template<int BM, int BN, int TM, int TN>
__global__ __launch_bounds__(256)
void k_sgemm(const float* __restrict__ A, const float* __restrict__ Bm,
             const float* __restrict__ bias, float* __restrict__ C,
             int M, int N, int K) {
    const int BK = 16;
    __shared__ float As[BK][BM];
    __shared__ float Bs[BK][BN];
    int tid = threadIdx.x;
    int tx = tid % (BN/TN), ty = tid / (BN/TN);
    int m0 = blockIdx.y * BM, n0 = blockIdx.x * BN;
    float acc[TM][TN];
#pragma unroll
    for (int i = 0; i < TM; i++)
#pragma unroll
        for (int j = 0; j < TN; j++) acc[i][j] = 0.f;
    for (int k0 = 0; k0 < K; k0 += BK) {
#pragma unroll
        for (int r = 0; r < (BM*BK)/1024; r++) {
            int idx = tid + r*256, mm = idx/(BK/4), kk4 = idx%(BK/4);
            float4 a = *(const float4*)&A[(size_t)(m0+mm)*K + k0 + kk4*4];
            As[kk4*4+0][mm]=a.x; As[kk4*4+1][mm]=a.y; As[kk4*4+2][mm]=a.z; As[kk4*4+3][mm]=a.w;
        }
#pragma unroll
        for (int r = 0; r < (BK*BN)/1024; r++) {
            int idx = tid + r*256, kk = idx/(BN/4), nn4 = idx%(BN/4);
            *(float4*)&Bs[kk][nn4*4] = *(const float4*)&Bm[(size_t)(k0+kk)*N + n0 + nn4*4];
        }
        __syncthreads();
#pragma unroll
        for (int kk = 0; kk < BK; kk++) {
            float ra[TM], rb[TN];
#pragma unroll
            for (int i = 0; i < TM; i += 4) *(float4*)&ra[i] = *(float4*)&As[kk][ty*TM+i];
#pragma unroll
            for (int j = 0; j < TN; j += 4) *(float4*)&rb[j] = *(float4*)&Bs[kk][tx*TN+j];
#pragma unroll
            for (int i = 0; i < TM; i++)
#pragma unroll
                for (int j = 0; j < TN; j++) acc[i][j] += ra[i]*rb[j];
        }
        __syncthreads();
    }
#pragma unroll
    for (int i = 0; i < TM; i++) {
        int m = m0 + ty*TM + i;
#pragma unroll
        for (int j = 0; j < TN; j += 4) {
            int n = n0 + tx*TN + j;
            float4 r;
            r.x = acc[i][j+0] + (bias ? bias[n+0] : 0.f);
            r.y = acc[i][j+1] + (bias ? bias[n+1] : 0.f);
            r.z = acc[i][j+2] + (bias ? bias[n+2] : 0.f);
            r.w = acc[i][j+3] + (bias ? bias[n+3] : 0.f);
            *(float4*)&C[(size_t)m*N + n] = r;
        }
    }
}

// ---------------- monolithic block-local decode loop ----------------
// smem: shB 2x24576 | h1 8x260 | h2 8x260 | q 8x260 | v 256 | su 800 | nxt 8i | cand 800B | pi 800B | mbar 32B
#define FLOATS_MAIN (49152 + 3*8*HR + 256 + 800)
#define MBAR_OFF_BYTES (FLOATS_MAIN*4 + 8*4 + 800 + 800)
#define SMEM_BYTES (MBAR_OFF_BYTES + 32)
#define NTILES_TOTAL (Nn*16)

__global__ __launch_bounds__(NT, 1)
void k_loop(const float* __restrict__ G,  const float* __restrict__ G0,
            const float* __restrict__ REF,
            const float* __restrict__ W2P, const float* __restrict__ WqP,
            const float* __restrict__ b_hh1,
            const float* __restrict__ b_ih2, const float* __restrict__ b_hh2,
            const float* __restrict__ v,   const float* __restrict__ wD,
            const float* __restrict__ x,   float* __restrict__ out) {
    extern __shared__ float sm[];
    float* shB   = sm;                    // 2 x 24576
    float* sh_h1 = sm + 49152;            // 8 x 260
    float* sh_h2 = sh_h1 + 8*HR;
    float* sh_q  = sh_h2 + 8*HR;
    float* sh_v  = sh_q + 8*HR;
    float* sh_su = sh_v + 256;            // su by LIST POSITION: [row][i]
    int*   sh_nxt = (int*)(sh_su + 800);
    unsigned char* sh_cand = (unsigned char*)(sh_nxt + 8);   // candidate lists
    unsigned char* sh_pi   = sh_cand + 800;

    const uint32_t base = smem_u32(sm);
    const uint32_t SHBa = base;
    const uint32_t MB   = base + MBAR_OFF_BYTES;   // DATA0,DATA1,CONS0,CONS1

    const int tid = threadIdx.x, lane = tid & 31, w = tid >> 5;
    const int b0 = blockIdx.x * 8;
    // pair mapping: threads (2t,2t+1) share column triplet j0, split rows 0-3 / 4-7
    const int j0 = (tid >> 1) & 255, rh = tid & 1;

    for (int i = tid; i < 800; i += NT) sh_cand[i] = (unsigned char)(i % 100);
    if (tid < 256) sh_v[tid] = __ldg(v + tid);

    const float bi2r = __ldg(b_ih2 + j0),       bh2r = __ldg(b_hh2 + j0);
    const float bi2z = __ldg(b_ih2 + 256 + j0), bh2z = __ldg(b_hh2 + 256 + j0);
    const float bi2n = __ldg(b_ih2 + 512 + j0), bh2n = __ldg(b_hh2 + 512 + j0);

    // ---- weight tile stream: g = 16*t + i ; i<8 -> W2P 96KB ; i>=8 -> WqP 32KB ----
    // buffer = g&1 ; parity (DATA & CONSUME) = (g>>1)&1.
    if (tid == 0) {
        mbar_init(MB, 1);       // DATA0
        mbar_init(MB + 8, 1);   // DATA1
        mbar_init(MB + 16, 16); // CONSUME0 (one arrive per warp)
        mbar_init(MB + 24, 16); // CONSUME1
    }
    __syncthreads();
    if (tid == 0) {
        mbar_expect_tx(MB, 98304u);
        bulk_g2s(SHBa, W2P, 98304u, MB);
        mbar_expect_tx(MB + 8, 98304u);
        bulk_g2s(SHBa + 98304u, W2P + 24576, 98304u, MB + 8);
    }

    float Dv = 1.0f, ll = 0.0f;

#pragma unroll 1
    for (int t = 0; t < Nn; t++) {
        // ---- A: GRU1 (h=0) -> sh_h1 (padded rows) ----
#pragma unroll
        for (int c = 0; c < 4; c++) {
            int idx = tid + c*NT;              // 2048 outputs
            int row = idx >> 8, j = idx & 255;
            const float* gsrc = (t == 0) ? (G0 + (size_t)(b0 + row)*H3)
                                         : (G + ((size_t)(b0 + row)*Nn + sh_nxt[row])*H3);
            float gr = __ldg(gsrc+j), gz = __ldg(gsrc+j+256), gn = __ldg(gsrc+j+512);
            if (t > 0) {
                gr = fmaf(Dv, __ldg(wD+j),     gr);
                gz = fmaf(Dv, __ldg(wD+j+256), gz);
                gn = fmaf(Dv, __ldg(wD+j+512), gn);
            }
            float rr = sigmoidf_(gr + __ldg(b_hh1+j));
            float zz = sigmoidf_(gz + __ldg(b_hh1+j+256));
            float nn = fast_tanh(fmaf(rr, __ldg(b_hh1+j+512), gn));
            sh_h1[row*HR + j] = (1.f - zz) * nn;
        }
        __syncthreads();

        // ---- B: GEMM2 (gi2 = h1 @ W2T) + fused GRU2 -> sh_h2 ----
        {
            float acc0[4], acc1[4], acc2[4];
#pragma unroll
            for (int r = 0; r < 4; r++) { acc0[r]=0.f; acc1[r]=0.f; acc2[r]=0.f; }
#pragma unroll 1
            for (int tile = 0; tile < 8; tile++) {
                const int g = t*16 + tile;
                const uint32_t b = g & 1, par = (g >> 1) & 1;
                mbar_wait(MB + b*8, par);
                const float* Bt = shB + b*24576;
#pragma unroll
                for (int kk4 = 0; kk4 < 8; kk4++) {
                    const float* bp = Bt + kk4*3072 + j0*4;
                    float4 bb0 = *(const float4*)bp;
                    float4 bb1 = *(const float4*)(bp + 1024);
                    float4 bb2 = *(const float4*)(bp + 2048);
#pragma unroll
                    for (int r = 0; r < 4; r++) {
                        float4 a = *(const float4*)(sh_h1 + (rh*4+r)*HR + tile*32 + kk4*4);
                        acc0[r] = dot4(a, bb0, acc0[r]);
                        acc1[r] = dot4(a, bb1, acc1[r]);
                        acc2[r] = dot4(a, bb2, acc2[r]);
                    }
                }
                // per-warp consume arrive (all lanes' loads already consumed by FMAs)
                __syncwarp();
                if (lane == 0) mbar_arrive(MB + 16 + b*8);
                if (tid == 0 && g + 2 < NTILES_TOTAL) {
                    mbar_wait(MB + 16 + b*8, par);     // all 16 warps consumed buffer b
                    const int g2 = g + 2, s2 = g2 & 15;
                    if (s2 < 8) {
                        mbar_expect_tx(MB + b*8, 98304u);
                        bulk_g2s(SHBa + b*98304u, W2P + s2*24576, 98304u, MB + b*8);
                    } else {
                        mbar_expect_tx(MB + b*8, 32768u);
                        bulk_g2s(SHBa + b*98304u, WqP + (s2-8)*8192, 32768u, MB + b*8);
                    }
                }
            }
#pragma unroll
            for (int r = 0; r < 4; r++) {
                float rr = sigmoidf_((acc0[r] + bi2r) + bh2r);
                float zz = sigmoidf_((acc1[r] + bi2z) + bh2z);
                float nn = fast_tanh(fmaf(rr, bh2n, acc2[r] + bi2n));
                sh_h2[(rh*4+r)*HR + j0] = (1.f - zz) * nn;
            }
        }
        __syncthreads();

        // ---- C: GEMM3 (q = h2 @ Wq) -> sh_q ----
        {
            float qa[4];
#pragma unroll
            for (int r = 0; r < 4; r++) qa[r] = 0.f;
#pragma unroll 1
            for (int tile = 0; tile < 8; tile++) {
                const int g = t*16 + 8 + tile;
                const uint32_t b = g & 1, par = (g >> 1) & 1;
                mbar_wait(MB + b*8, par);
                const float* Bt = shB + b*24576;
#pragma unroll
                for (int kk4 = 0; kk4 < 8; kk4++) {
                    float4 bb = *(const float4*)(Bt + kk4*1024 + j0*4);
#pragma unroll
                    for (int r = 0; r < 4; r++) {
                        float4 a = *(const float4*)(sh_h2 + (rh*4+r)*HR + tile*32 + kk4*4);
                        qa[r] = dot4(a, bb, qa[r]);
                    }
                }
                __syncwarp();
                if (lane == 0) mbar_arrive(MB + 16 + b*8);
                if (tid == 0 && g + 2 < NTILES_TOTAL) {
                    mbar_wait(MB + 16 + b*8, par);
                    const int g2 = g + 2, s2 = g2 & 15;
                    if (s2 < 8) {
                        mbar_expect_tx(MB + b*8, 98304u);
                        bulk_g2s(SHBa + b*98304u, W2P + s2*24576, 98304u, MB + b*8);
                    } else {
                        mbar_expect_tx(MB + b*8, 32768u);
                        bulk_g2s(SHBa + b*98304u, WqP + (s2-8)*8192, 32768u, MB + b*8);
                    }
                }
            }
#pragma unroll
            for (int r = 0; r < 4; r++) sh_q[(rh*4+r)*HR + j0] = qa[r];
        }
        __syncthreads();

        // ---- D: attention over candidate list, 2 warps/row, depth-2 prefetch ----
        {
            const int w2i = w >> 1, parr = w & 1;
            const int cnt = Nn - t;
            const int R = b0 + w2i;
            float4 q0 = *(const float4*)(sh_q + w2i*HR + lane*4);
            float4 q1 = *(const float4*)(sh_q + w2i*HR + 128 + lane*4);
            float4 v0 = *(const float4*)(sh_v + lane*4);
            float4 v1 = *(const float4*)(sh_v + 128 + lane*4);
            const float4* refrow = (const float4*)(REF + (size_t)R*Nn*Hh);
            const unsigned char* cl = sh_cand + w2i*100;
            int i = parr;
            float4 ra0, rb0, ra1, rb1;
            if (i < cnt) {
                int n0i = cl[i];
                ra0 = __ldg(refrow + n0i*64 + lane);
                rb0 = __ldg(refrow + n0i*64 + 32 + lane);
            }
            if (i + 2 < cnt) {
                int n1i = cl[i + 2];
                ra1 = __ldg(refrow + n1i*64 + lane);
                rb1 = __ldg(refrow + n1i*64 + 32 + lane);
            }
#pragma unroll 1
            for (; i < cnt; i += 2) {
                int nnx = (i + 4 < cnt) ? cl[i + 4] : 0;
                float4 ra2 = __ldg(refrow + nnx*64 + lane);
                float4 rb2 = __ldg(refrow + nnx*64 + 32 + lane);
                float s = tanh4dot(q0, ra0, v0) + tanh4dot(q1, rb0, v1);
#pragma unroll
                for (int o = 16; o; o >>= 1) s += __shfl_xor_sync(~0u, s, o);
                if (lane == 0) sh_su[w2i*100 + i] = 10.f * fast_tanh(s);
                ra0 = ra1; rb0 = rb1; ra1 = ra2; rb1 = rb2;
            }
        }
        __syncthreads();
        // argmax / log-softmax / state: warp w handles row w (w < 8)
        if (w < 8) {
            const int cnt = Nn - t;
            float best = -INFINITY; int bidx = 0x7fffffff; int bpos = 0;
            for (int i = lane; i < cnt; i += 32) {
                float u = sh_su[w*100 + i];
                int n = sh_cand[w*100 + i];
                if (u > best || (u == best && n < bidx)) { best = u; bidx = n; bpos = i; }
            }
#pragma unroll
            for (int o = 16; o; o >>= 1) {
                float ov = __shfl_xor_sync(~0u, best, o);
                int   oi = __shfl_xor_sync(~0u, bidx, o);
                int   op = __shfl_xor_sync(~0u, bpos, o);
                if (ov > best || (ov == best && oi < bidx)) { best = ov; bidx = oi; bpos = op; }
            }
            float se = 0.f;
            for (int i = lane; i < cnt; i += 32) se += __expf(sh_su[w*100 + i] - best);
#pragma unroll
            for (int o = 16; o; o >>= 1) se += __shfl_xor_sync(~0u, se, o);
            ll += -__logf(se);
            if (lane == 0) {
                sh_nxt[w] = bidx;
                sh_pi[w*100 + t] = (unsigned char)bidx;
                sh_cand[w*100 + bpos] = sh_cand[w*100 + cnt - 1];   // swap-remove
            }
        }
        __syncthreads();
        Dv -= 0.01f;
    }

    // ---- tour cost + output: warp w handles row w (w < 8) ----
    if (w < 8) {
        float cs = 0.f;
        const float* xb = x + (size_t)(b0 + w)*Nn*2;
        for (int tt = lane; tt < Nn; tt += 32) {
            int a  = sh_pi[w*100 + tt];
            int cc = sh_pi[w*100 + ((tt == Nn-1) ? 0 : tt+1)];
            float dx = __ldg(xb + a*2)     - __ldg(xb + cc*2);
            float dy = __ldg(xb + a*2 + 1) - __ldg(xb + cc*2 + 1);
            cs += sqrtf(dx*dx + dy*dy);
        }
#pragma unroll
        for (int o = 16; o; o >>= 1) cs += __shfl_xor_sync(~0u, cs, o);
        if (lane == 0) { out[b0 + w] = cs; out[Bsz + b0 + w] = ll; }
    }
}

// ---------------- launcher ----------------
extern "C" void kernel_launch(void* const* d_in, const int* in_sizes, int n_in,
                              void* d_out, int out_size) {
    const float* x     = (const float*)d_in[0];
    const float* enc   = (const float*)d_in[1];
    const float* W_ih1 = (const float*)d_in[2];
    const float* b_ih1 = (const float*)d_in[4];
    const float* b_hh1 = (const float*)d_in[5];
    const float* W_ih2 = (const float*)d_in[6];
    const float* b_ih2 = (const float*)d_in[8];
    const float* b_hh2 = (const float*)d_in[9];
    const float* W_q   = (const float*)d_in[10];
    const float* W_ref = (const float*)d_in[11];
    const float* v     = (const float*)d_in[12];
    float* out = (float*)d_out;

    float *G, *REF, *G0, *MEAN, *W1T, *W2P, *WqP, *BIAS0, *WD;
    cudaGetSymbolAddress((void**)&G,    g_G);
    cudaGetSymbolAddress((void**)&REF,  g_ref);
    cudaGetSymbolAddress((void**)&G0,   g_G0);
    cudaGetSymbolAddress((void**)&MEAN, g_mean);
    cudaGetSymbolAddress((void**)&W1T,  g_W1T);
    cudaGetSymbolAddress((void**)&W2P,  g_W2P);
    cudaGetSymbolAddress((void**)&WqP,  g_WqP);
    cudaGetSymbolAddress((void**)&BIAS0,g_bias0);
    cudaGetSymbolAddress((void**)&WD,   g_wD);

    cudaFuncSetAttribute(k_loop, cudaFuncAttributeMaxDynamicSharedMemorySize, SMEM_BYTES);

    k_prep<<<768, 256>>>(W_ih1, W_ih2, W_q, b_ih1);
    k_mean<<<Bsz, 256>>>(enc);
    k_sgemm<128,128,8,8><<<dim3(H3/128, (Bsz*Nn)/128), 256>>>(enc, W1T, b_ih1, G, Bsz*Nn, H3, Hh);
    k_sgemm<128,128,8,8><<<dim3(Hh/128, (Bsz*Nn)/128), 256>>>(enc, W_ref, nullptr, REF, Bsz*Nn, Hh, Hh);
    k_sgemm<64,64,4,4><<<dim3(H3/64, Bsz/64), 256>>>(MEAN, W1T, BIAS0, G0, Bsz, H3, Hh);
    k_loop<<<NBLK, NT, SMEM_BYTES>>>(G, G0, REF, W2P, WqP, b_hh1, b_ih2, b_hh2, v, WD, x, out);
}